// round 8
// baseline (speedup 1.0000x reference)
#include <cuda_runtime.h>
#include <cuda_bf16.h>
#include <cstdint>

// Problem constants
#define BATCH 128
#define HEADS 12
#define NTOK  197
#define CDIM  768
#define HD    64
#define MROWS (BATCH * NTOK) // 25216
#define KDIM  768
#define N_QKV (3 * CDIM)     // 2304

// -------- fp32 scratch --------
__device__ float g_q [BATCH * HEADS * NTOK * HD];
__device__ float g_k [BATCH * HEADS * NTOK * HD];
__device__ float g_v [BATCH * HEADS * NTOK * HD];
__device__ float g_rb[HEADS * NTOK * NTOK];

// -------- bf16 split scratch (big/small pairs) --------
__device__ __nv_bfloat16 g_xb [MROWS * KDIM];
__device__ __nv_bfloat16 g_xs [MROWS * KDIM];
__device__ __nv_bfloat16 g_wqb[N_QKV * KDIM];
__device__ __nv_bfloat16 g_wqs[N_QKV * KDIM];
__device__ __nv_bfloat16 g_wpb[CDIM * CDIM];
__device__ __nv_bfloat16 g_wps[CDIM * CDIM];
__device__ __nv_bfloat16 g_aob[MROWS * CDIM];
__device__ __nv_bfloat16 g_aos[MROWS * CDIM];

// ======================= rel-pos bias gather =======================
__global__ void relbias_kernel(const float* __restrict__ table,
                               const int* __restrict__ idx) {
    int i = blockIdx.x * 256 + threadIdx.x;
    if (i < NTOK * NTOK) {
        int id = idx[i];
#pragma unroll
        for (int h = 0; h < HEADS; h++)
            g_rb[h * NTOK * NTOK + i] = table[id * HEADS + h];
    }
}

// ======================= fp32 -> bf16{big,small} split =======================
__device__ __forceinline__ void split1(float v, __nv_bfloat16& b, __nv_bfloat16& s) {
    b = __float2bfloat16_rn(v);
    s = __float2bfloat16_rn(v - __bfloat162float(b));
}

__global__ void split_kernel(const float* __restrict__ src,
                             __nv_bfloat16* __restrict__ big,
                             __nv_bfloat16* __restrict__ small, int n4) {
    int i = blockIdx.x * 256 + threadIdx.x;
    if (i < n4) {
        float4 v = *(const float4*)&src[i * 4];
        __nv_bfloat16 b0,s0,b1,s1,b2,s2,b3,s3;
        split1(v.x,b0,s0); split1(v.y,b1,s1); split1(v.z,b2,s2); split1(v.w,b3,s3);
        *(__nv_bfloat162*)&big  [i*4    ] = {b0,b1};
        *(__nv_bfloat162*)&big  [i*4 + 2] = {b2,b3};
        *(__nv_bfloat162*)&small[i*4    ] = {s0,s1};
        *(__nv_bfloat162*)&small[i*4 + 2] = {s2,s3};
    }
}

// ======================= bf16 3-pass GEMM: 3-stage cp.async pipeline ==========
// C[m,n] = sum_k A[m,k]*B[n,k]. CTA 128x64, k-chunk 32, 8 warps (4M x 2N),
// warp tile 32x32. THREE cp.async stages, ONE __syncthreads per k-chunk:
// load(t+2) targets the buffer of t-1, already drained by this iteration's
// barrier, so no trailing barrier is needed.
#define GBK 32
#define NKT (KDIM / GBK)     // 24
#define OFF_AB 0
#define OFF_AS 8192
#define OFF_BB 16384
#define OFF_BS 20480
#define STG    24576
#define NSTG   3
#define SMEM_GEMM (NSTG * STG)  // 73728

__device__ __forceinline__ uint32_t smem_u32(const void* p) {
    uint32_t a;
    asm("{ .reg .u64 t; cvta.to.shared.u64 t, %1; cvt.u32.u64 %0, t; }" : "=r"(a) : "l"(p));
    return a;
}
__device__ __forceinline__ void cp16(uint32_t d, const void* s) {
    asm volatile("cp.async.cg.shared.global [%0], [%1], 16;" :: "r"(d), "l"(s));
}
__device__ __forceinline__ void ldsm4(unsigned& a0, unsigned& a1, unsigned& a2, unsigned& a3,
                                      uint32_t addr) {
    asm volatile("ldmatrix.sync.aligned.m8n8.x4.shared.b16 {%0,%1,%2,%3}, [%4];"
        : "=r"(a0), "=r"(a1), "=r"(a2), "=r"(a3) : "r"(addr));
}
__device__ __forceinline__ void mma16(float* c, const unsigned* a, const unsigned* b) {
    asm volatile("mma.sync.aligned.m16n8k16.row.col.f32.bf16.bf16.f32 "
        "{%0,%1,%2,%3}, {%4,%5,%6,%7}, {%8,%9}, {%0,%1,%2,%3};"
        : "+f"(c[0]), "+f"(c[1]), "+f"(c[2]), "+f"(c[3])
        : "r"(a[0]), "r"(a[1]), "r"(a[2]), "r"(a[3]), "r"(b[0]), "r"(b[1]));
}

// swizzled byte offset within a 64B-row buffer: row r, 16B chunk c (0..3)
__device__ __forceinline__ uint32_t sw_off(int r, int c) {
    return (uint32_t)(r * 64 + ((c ^ ((r >> 1) & 3)) << 4));
}

// issue cp.async for one k-chunk into stage buffer
__device__ __forceinline__ void load_stage(
    uint32_t sb,
    const __nv_bfloat16* __restrict__ Ab, const __nv_bfloat16* __restrict__ As,
    const __nv_bfloat16* __restrict__ Bb, const __nv_bfloat16* __restrict__ Bs,
    int m0, int n0, int kt, int tid) {
#pragma unroll
    for (int i = 0; i < 2; i++) {          // A: 128 rows x 4 chunks = 512
        int id = i * 256 + tid;
        int r = id >> 2, c = id & 3;
        size_t src = (size_t)(m0 + r) * KDIM + kt + c * 8;
        uint32_t d = sw_off(r, c);
        cp16(sb + OFF_AB + d, Ab + src);
        cp16(sb + OFF_AS + d, As + src);
    }
    {                                       // B: 64 rows x 4 chunks = 256
        int r = tid >> 2, c = tid & 3;
        size_t src = (size_t)(n0 + r) * KDIM + kt + c * 8;
        uint32_t d = sw_off(r, c);
        cp16(sb + OFF_BB + d, Bb + src);
        cp16(sb + OFF_BS + d, Bs + src);
    }
    asm volatile("cp.async.commit_group;" ::: "memory");
}

__device__ __forceinline__ void gemm_mainloop(
    const __nv_bfloat16* __restrict__ Ab, const __nv_bfloat16* __restrict__ As,
    const __nv_bfloat16* __restrict__ Bb, const __nv_bfloat16* __restrict__ Bs,
    int m0, int n0, uint32_t smem_base, float acc[2][4][4]) {

    const int tid = threadIdx.x;
    const int lane = tid & 31, warp = tid >> 5;
    const int mbase = (warp & 3) * 32;
    const int nbase = (warp >> 2) * 32;

#pragma unroll
    for (int a = 0; a < 2; a++)
#pragma unroll
        for (int b = 0; b < 4; b++)
#pragma unroll
            for (int c = 0; c < 4; c++) acc[a][b][c] = 0.f;

    // per-lane ldmatrix row/chunk components
    const int a_row = mbase + (lane & 15);          // + mt*16
    const int a_hi  = lane >> 4;                    // k 16B half
    const int b_row = nbase + (lane & 7) + ((lane >> 4) & 1) * 8;  // + bt*16
    const int b_hi  = (lane >> 3) & 1;

    // prologue: stages 0,1 <- tiles 0,1
    load_stage(smem_base,       Ab, As, Bb, Bs, m0, n0, 0,   tid);
    load_stage(smem_base + STG, Ab, As, Bb, Bs, m0, n0, GBK, tid);

    int s = 0;
    for (int t = 0; t < NKT; t++) {
        if (t + 1 < NKT) asm volatile("cp.async.wait_group 1;" ::: "memory");
        else             asm volatile("cp.async.wait_group 0;" ::: "memory");
        __syncthreads();   // tile t resident for all warps; buffer of t-1 drained

        if (t + 2 < NKT) {
            int s2 = s + 2; if (s2 >= NSTG) s2 -= NSTG;
            load_stage(smem_base + s2 * STG, Ab, As, Bb, Bs, m0, n0, (t + 2) * GBK, tid);
        }

        uint32_t sb = smem_base + s * STG;
#pragma unroll
        for (int kk = 0; kk < 2; kk++) {
            unsigned Afb[2][4], Afs[2][4], Bfb[4][2], Bfs[4][2];
#pragma unroll
            for (int mt = 0; mt < 2; mt++) {
                int r = a_row + mt * 16;
                uint32_t off = sw_off(r, kk * 2 + a_hi);
                ldsm4(Afb[mt][0], Afb[mt][1], Afb[mt][2], Afb[mt][3], sb + OFF_AB + off);
                ldsm4(Afs[mt][0], Afs[mt][1], Afs[mt][2], Afs[mt][3], sb + OFF_AS + off);
            }
#pragma unroll
            for (int bt = 0; bt < 2; bt++) {
                int r = b_row + bt * 16;
                uint32_t off = sw_off(r, kk * 2 + b_hi);
                ldsm4(Bfb[bt*2][0], Bfb[bt*2][1], Bfb[bt*2+1][0], Bfb[bt*2+1][1],
                      sb + OFF_BB + off);
                ldsm4(Bfs[bt*2][0], Bfs[bt*2][1], Bfs[bt*2+1][0], Bfs[bt*2+1][1],
                      sb + OFF_BS + off);
            }
#pragma unroll
            for (int mt = 0; mt < 2; mt++)
#pragma unroll
                for (int nt = 0; nt < 4; nt++) {
                    mma16(acc[mt][nt], Afb[mt], Bfb[nt]);  // big*big
                    mma16(acc[mt][nt], Afb[mt], Bfs[nt]);  // big*small
                    mma16(acc[mt][nt], Afs[mt], Bfb[nt]);  // small*big
                }
        }
        s = (s + 1 == NSTG) ? 0 : s + 1;
    }
}

// ---- QKV GEMM: bx in 0..35; which = bx/12, h = bx%12; scatter epilogue ----
__global__ __launch_bounds__(256, 2)
void qkv_gemm_kernel(const float* __restrict__ q_bias, const float* __restrict__ v_bias) {
    extern __shared__ char smg[];
    const int bx = blockIdx.x, m0 = blockIdx.y * 128;
    float acc[2][4][4];
    gemm_mainloop(g_xb, g_xs, g_wqb, g_wqs, m0, bx * 64, smem_u32(smg), acc);

    const int lane = threadIdx.x & 31, warp = threadIdx.x >> 5;
    const int tig = lane & 3, gid = lane >> 2;
    const int mbase = (warp & 3) * 32, nbase = (warp >> 2) * 32;
    const int which = bx / HEADS, h = bx % HEADS;
    const float scale = 0.125f;

#pragma unroll
    for (int mt = 0; mt < 2; mt++)
#pragma unroll
        for (int nt = 0; nt < 4; nt++) {
            int d = nbase + nt * 8 + tig * 2;
#pragma unroll
            for (int half = 0; half < 2; half++) {
                int m = m0 + mbase + mt * 16 + gid + half * 8;
                int b_i = m / NTOK, tok = m % NTOK;
                size_t base = ((size_t)(b_i * HEADS + h) * NTOK + tok) * HD + d;
                float2 o = make_float2(acc[mt][nt][half * 2 + 0], acc[mt][nt][half * 2 + 1]);
                if (which == 0) {
                    float2 qb = *(const float2*)&q_bias[h * HD + d];
                    o.x = (o.x + qb.x) * scale;
                    o.y = (o.y + qb.y) * scale;
                    *(float2*)&g_q[base] = o;
                } else if (which == 1) {
                    *(float2*)&g_k[base] = o;
                } else {
                    float2 vb = *(const float2*)&v_bias[h * HD + d];
                    o.x += vb.x; o.y += vb.y;
                    *(float2*)&g_v[base] = o;
                }
            }
        }
}

// ---- output projection GEMM ----
__global__ __launch_bounds__(256, 2)
void proj_gemm_kernel(const float* __restrict__ bias, float* __restrict__ out) {
    extern __shared__ char smg[];
    const int bx = blockIdx.x, m0 = blockIdx.y * 128;
    float acc[2][4][4];
    gemm_mainloop(g_aob, g_aos, g_wpb, g_wps, m0, bx * 64, smem_u32(smg), acc);

    const int lane = threadIdx.x & 31, warp = threadIdx.x >> 5;
    const int tig = lane & 3, gid = lane >> 2;
    const int mbase = (warp & 3) * 32, nbase = (warp >> 2) * 32;

#pragma unroll
    for (int mt = 0; mt < 2; mt++)
#pragma unroll
        for (int nt = 0; nt < 4; nt++) {
            int ng = bx * 64 + nbase + nt * 8 + tig * 2;
            float2 bb = *(const float2*)&bias[ng];
#pragma unroll
            for (int half = 0; half < 2; half++) {
                int m = m0 + mbase + mt * 16 + gid + half * 8;
                float2 o = make_float2(acc[mt][nt][half * 2 + 0] + bb.x,
                                       acc[mt][nt][half * 2 + 1] + bb.y);
                *(float2*)&out[(size_t)m * CDIM + ng] = o;
            }
        }
}

// ======================= attention (q-blocked SIMT, unchanged) =======================
#define QBLK 4
#define NQG  ((NTOK + QBLK - 1) / QBLK)  // 50
#define KPAD 68
#define PSTR 5
#define SM_K (NTOK * KPAD)
#define SM_V (NTOK * HD)
#define SM_P (8 * 200 * PSTR)
#define SM_Q (8 * QBLK * HD)
#define SMEM_ATTN ((SM_K + SM_V + SM_P + SM_Q) * 4)  // 144208 B

__global__ __launch_bounds__(256)
void attn_kernel() {
    extern __shared__ float sma[];
    float* Ks = sma;
    float* Vs = Ks + SM_K;
    float* Ps = Vs + SM_V;
    float* Qs = Ps + SM_P;

    const int bh = blockIdx.x;
    const int b = bh / HEADS, h = bh % HEADS;
    const int tid = threadIdx.x;
    const float* kb = g_k + (size_t)bh * NTOK * HD;
    const float* vb = g_v + (size_t)bh * NTOK * HD;
    const float* qg = g_q + (size_t)bh * NTOK * HD;
    const float* rb = g_rb + (size_t)h * NTOK * NTOK;

    for (int e = tid; e < NTOK * (HD / 4); e += 256) {
        int row = e >> 4, c4 = (e & 15) << 2;
        *(float4*)&Ks[row * KPAD + c4] = *(const float4*)&kb[row * HD + c4];
        *(float4*)&Vs[row * HD + c4]   = *(const float4*)&vb[row * HD + c4];
    }
    __syncthreads();

    const int w = tid >> 5, lane = tid & 31;
    float* Pw = Ps + w * 200 * PSTR;
    float* Qw = Qs + w * QBLK * HD;

    for (int qgi = w; qgi < NQG; qgi += 8) {
        const int q0 = qgi * QBLK;
#pragma unroll
        for (int qq = 0; qq < QBLK; qq++) {
            int q = q0 + qq;
            float2 qv = (q < NTOK) ? *(const float2*)&qg[(size_t)q * HD + lane * 2]
                                   : make_float2(0.f, 0.f);
            *(float2*)&Qw[qq * HD + lane * 2] = qv;
        }
        __syncwarp();

        float s[QBLK][7];
#pragma unroll
        for (int i = 0; i < 7; i++) {
            int m = lane + i * 32;
            if (m < NTOK) {
                float a[QBLK] = {0.f, 0.f, 0.f, 0.f};
#pragma unroll
                for (int d4 = 0; d4 < 16; d4++) {
                    float4 kk = *(const float4*)&Ks[m * KPAD + d4 * 4];
#pragma unroll
                    for (int qq = 0; qq < QBLK; qq++) {
                        float4 qf = *(const float4*)&Qw[qq * HD + d4 * 4];
                        a[qq] = fmaf(kk.x, qf.x, a[qq]);
                        a[qq] = fmaf(kk.y, qf.y, a[qq]);
                        a[qq] = fmaf(kk.z, qf.z, a[qq]);
                        a[qq] = fmaf(kk.w, qf.w, a[qq]);
                    }
                }
#pragma unroll
                for (int qq = 0; qq < QBLK; qq++) {
                    int q = q0 + qq;
                    s[qq][i] = a[qq] + ((q < NTOK) ? rb[(size_t)q * NTOK + m] : 0.f);
                }
            } else {
#pragma unroll
                for (int qq = 0; qq < QBLK; qq++) s[qq][i] = -1e30f;
            }
        }
#pragma unroll
        for (int qq = 0; qq < QBLK; qq++) {
            float mx = s[qq][0];
#pragma unroll
            for (int i = 1; i < 7; i++) mx = fmaxf(mx, s[qq][i]);
#pragma unroll
            for (int o = 16; o > 0; o >>= 1) mx = fmaxf(mx, __shfl_xor_sync(0xffffffffu, mx, o));
            float sum = 0.f;
#pragma unroll
            for (int i = 0; i < 7; i++) {
                int m = lane + i * 32;
                s[qq][i] = (m < NTOK) ? __expf(s[qq][i] - mx) : 0.f;
                sum += s[qq][i];
            }
#pragma unroll
            for (int o = 16; o > 0; o >>= 1) sum += __shfl_xor_sync(0xffffffffu, sum, o);
            float inv = 1.f / sum;
#pragma unroll
            for (int i = 0; i < 7; i++) {
                int m = lane + i * 32;
                if (m < NTOK) Pw[m * PSTR + qq] = s[qq][i] * inv;
            }
        }
        __syncwarp();

        float2 o2[QBLK] = {{0.f,0.f},{0.f,0.f},{0.f,0.f},{0.f,0.f}};
        for (int m = 0; m < NTOK; m++) {
            float2 vv = *(const float2*)&Vs[m * HD + lane * 2];
            float p0 = Pw[m * PSTR + 0];
            float p1 = Pw[m * PSTR + 1];
            float p2 = Pw[m * PSTR + 2];
            float p3 = Pw[m * PSTR + 3];
            o2[0].x = fmaf(p0, vv.x, o2[0].x); o2[0].y = fmaf(p0, vv.y, o2[0].y);
            o2[1].x = fmaf(p1, vv.x, o2[1].x); o2[1].y = fmaf(p1, vv.y, o2[1].y);
            o2[2].x = fmaf(p2, vv.x, o2[2].x); o2[2].y = fmaf(p2, vv.y, o2[2].y);
            o2[3].x = fmaf(p3, vv.x, o2[3].x); o2[3].y = fmaf(p3, vv.y, o2[3].y);
        }
#pragma unroll
        for (int qq = 0; qq < QBLK; qq++) {
            int q = q0 + qq;
            if (q < NTOK) {
                size_t base = ((size_t)(b * NTOK + q)) * CDIM + h * HD + lane * 2;
                __nv_bfloat16 b0,s0,b1,s1;
                split1(o2[qq].x, b0, s0);
                split1(o2[qq].y, b1, s1);
                *(__nv_bfloat162*)&g_aob[base] = {b0, b1};
                *(__nv_bfloat162*)&g_aos[base] = {s0, s1};
            }
        }
        __syncwarp();
    }
}

// ======================= launch =======================
extern "C" void kernel_launch(void* const* d_in, const int* in_sizes, int n_in,
                              void* d_out, int out_size) {
    const float* x        = (const float*)d_in[0];
    const float* qkv_w    = (const float*)d_in[1];
    const float* q_bias   = (const float*)d_in[2];
    const float* v_bias   = (const float*)d_in[3];
    const float* rel_tab  = (const float*)d_in[4];
    const float* proj_w   = (const float*)d_in[5];
    const float* proj_b   = (const float*)d_in[6];
    const int*   rel_idx  = (const int*)d_in[7];
    float* out = (float*)d_out;

    static_assert(MROWS % 128 == 0 && N_QKV % 64 == 0 && CDIM % 64 == 0, "tiling");

    cudaFuncSetAttribute(qkv_gemm_kernel,  cudaFuncAttributeMaxDynamicSharedMemorySize, SMEM_GEMM);
    cudaFuncSetAttribute(proj_gemm_kernel, cudaFuncAttributeMaxDynamicSharedMemorySize, SMEM_GEMM);
    cudaFuncSetAttribute(attn_kernel,      cudaFuncAttributeMaxDynamicSharedMemorySize, SMEM_ATTN);

    relbias_kernel<<<(NTOK * NTOK + 255) / 256, 256>>>(rel_tab, rel_idx);

    {
        __nv_bfloat16 *xb, *xs, *wqb, *wqs, *wpb, *wps;
        cudaGetSymbolAddress((void**)&xb,  g_xb);
        cudaGetSymbolAddress((void**)&xs,  g_xs);
        cudaGetSymbolAddress((void**)&wqb, g_wqb);
        cudaGetSymbolAddress((void**)&wqs, g_wqs);
        cudaGetSymbolAddress((void**)&wpb, g_wpb);
        cudaGetSymbolAddress((void**)&wps, g_wps);
        int n4x = MROWS * KDIM / 4;
        split_kernel<<<(n4x + 255) / 256, 256>>>(x, xb, xs, n4x);
        int n4q = N_QKV * KDIM / 4;
        split_kernel<<<(n4q + 255) / 256, 256>>>(qkv_w, wqb, wqs, n4q);
        int n4p = CDIM * CDIM / 4;
        split_kernel<<<(n4p + 255) / 256, 256>>>(proj_w, wpb, wps, n4p);
    }

    {
        dim3 grid(N_QKV / 64, MROWS / 128);  // (36, 197)
        qkv_gemm_kernel<<<grid, 256, SMEM_GEMM>>>(q_bias, v_bias);
    }

    attn_kernel<<<BATCH * HEADS, 256, SMEM_ATTN>>>();

    {
        dim3 grid(CDIM / 64, MROWS / 128);   // (12, 197)
        proj_gemm_kernel<<<grid, 256, SMEM_GEMM>>>(proj_b, out);
    }
}

// round 9
// speedup vs baseline: 1.1327x; 1.1327x over previous
#include <cuda_runtime.h>
#include <cuda_bf16.h>
#include <cstdint>

// Problem constants
#define BATCH 128
#define HEADS 12
#define NTOK  197
#define CDIM  768
#define HD    64
#define MROWS (BATCH * NTOK) // 25216
#define KDIM  768
#define N_QKV (3 * CDIM)     // 2304

// -------- fp32 scratch --------
__device__ float g_q [BATCH * HEADS * NTOK * HD];
__device__ float g_k [BATCH * HEADS * NTOK * HD];
__device__ float g_v [BATCH * HEADS * NTOK * HD];
__device__ float g_rb[HEADS * NTOK * NTOK];

// -------- bf16 split scratch (big/small pairs) --------
__device__ __nv_bfloat16 g_xb [MROWS * KDIM];
__device__ __nv_bfloat16 g_xs [MROWS * KDIM];
__device__ __nv_bfloat16 g_wqb[N_QKV * KDIM];
__device__ __nv_bfloat16 g_wqs[N_QKV * KDIM];
__device__ __nv_bfloat16 g_wpb[CDIM * CDIM];
__device__ __nv_bfloat16 g_wps[CDIM * CDIM];
__device__ __nv_bfloat16 g_aob[MROWS * CDIM];
__device__ __nv_bfloat16 g_aos[MROWS * CDIM];

// ======================= rel-pos bias gather =======================
__global__ void relbias_kernel(const float* __restrict__ table,
                               const int* __restrict__ idx) {
    int i = blockIdx.x * 256 + threadIdx.x;
    if (i < NTOK * NTOK) {
        int id = idx[i];
#pragma unroll
        for (int h = 0; h < HEADS; h++)
            g_rb[h * NTOK * NTOK + i] = table[id * HEADS + h];
    }
}

// ======================= fp32 -> bf16{big,small} split =======================
__device__ __forceinline__ void split1(float v, __nv_bfloat16& b, __nv_bfloat16& s) {
    b = __float2bfloat16_rn(v);
    s = __float2bfloat16_rn(v - __bfloat162float(b));
}

__global__ void split_kernel(const float* __restrict__ src,
                             __nv_bfloat16* __restrict__ big,
                             __nv_bfloat16* __restrict__ small, int n4) {
    int i = blockIdx.x * 256 + threadIdx.x;
    if (i < n4) {
        float4 v = *(const float4*)&src[i * 4];
        __nv_bfloat16 b0,s0,b1,s1,b2,s2,b3,s3;
        split1(v.x,b0,s0); split1(v.y,b1,s1); split1(v.z,b2,s2); split1(v.w,b3,s3);
        *(__nv_bfloat162*)&big  [i*4    ] = {b0,b1};
        *(__nv_bfloat162*)&big  [i*4 + 2] = {b2,b3};
        *(__nv_bfloat162*)&small[i*4    ] = {s0,s1};
        *(__nv_bfloat162*)&small[i*4 + 2] = {s2,s3};
    }
}

// ======================= bf16 3-pass GEMM: CTA 128x128, warp tile 64x32 ==========
// C[m,n] = sum_k A[m,k]*B[n,k]. k-chunk 32, 8 warps as 2(M) x 4(N).
// 3 cp.async stages, one barrier per k-chunk.
#define GBK 32
#define NKT (KDIM / GBK)     // 24
#define OFF_AB 0
#define OFF_AS 8192
#define OFF_BB 16384
#define OFF_BS 24576
#define STG    32768
#define NSTG   3
#define SMEM_GEMM (NSTG * STG)  // 98304

__device__ __forceinline__ uint32_t smem_u32(const void* p) {
    uint32_t a;
    asm("{ .reg .u64 t; cvta.to.shared.u64 t, %1; cvt.u32.u64 %0, t; }" : "=r"(a) : "l"(p));
    return a;
}
__device__ __forceinline__ void cp16(uint32_t d, const void* s) {
    asm volatile("cp.async.cg.shared.global [%0], [%1], 16;" :: "r"(d), "l"(s));
}
__device__ __forceinline__ void ldsm4(unsigned& a0, unsigned& a1, unsigned& a2, unsigned& a3,
                                      uint32_t addr) {
    asm volatile("ldmatrix.sync.aligned.m8n8.x4.shared.b16 {%0,%1,%2,%3}, [%4];"
        : "=r"(a0), "=r"(a1), "=r"(a2), "=r"(a3) : "r"(addr));
}
__device__ __forceinline__ void mma16(float* c, const unsigned* a, const unsigned* b) {
    asm volatile("mma.sync.aligned.m16n8k16.row.col.f32.bf16.bf16.f32 "
        "{%0,%1,%2,%3}, {%4,%5,%6,%7}, {%8,%9}, {%0,%1,%2,%3};"
        : "+f"(c[0]), "+f"(c[1]), "+f"(c[2]), "+f"(c[3])
        : "r"(a[0]), "r"(a[1]), "r"(a[2]), "r"(a[3]), "r"(b[0]), "r"(b[1]));
}

// swizzled byte offset within a 64B-row buffer: row r, 16B chunk c (0..3)
__device__ __forceinline__ uint32_t sw_off(int r, int c) {
    return (uint32_t)(r * 64 + ((c ^ ((r >> 1) & 3)) << 4));
}

// issue cp.async for one k-chunk: A 128 rows + B 128 rows, big+small
__device__ __forceinline__ void load_stage(
    uint32_t sb,
    const __nv_bfloat16* __restrict__ Ab, const __nv_bfloat16* __restrict__ As,
    const __nv_bfloat16* __restrict__ Bb, const __nv_bfloat16* __restrict__ Bs,
    int m0, int n0, int kt, int tid) {
#pragma unroll
    for (int i = 0; i < 2; i++) {
        int id = i * 256 + tid;
        int r = id >> 2, c = id & 3;
        size_t src = (size_t)(m0 + r) * KDIM + kt + c * 8;
        uint32_t d = sw_off(r, c);
        cp16(sb + OFF_AB + d, Ab + src);
        cp16(sb + OFF_AS + d, As + src);
    }
#pragma unroll
    for (int i = 0; i < 2; i++) {
        int id = i * 256 + tid;
        int r = id >> 2, c = id & 3;
        size_t src = (size_t)(n0 + r) * KDIM + kt + c * 8;
        uint32_t d = sw_off(r, c);
        cp16(sb + OFF_BB + d, Bb + src);
        cp16(sb + OFF_BS + d, Bs + src);
    }
    asm volatile("cp.async.commit_group;" ::: "memory");
}

__device__ __forceinline__ void gemm_mainloop(
    const __nv_bfloat16* __restrict__ Ab, const __nv_bfloat16* __restrict__ As,
    const __nv_bfloat16* __restrict__ Bb, const __nv_bfloat16* __restrict__ Bs,
    int m0, int n0, uint32_t smem_base, float acc[4][4][4]) {

    const int tid = threadIdx.x;
    const int lane = tid & 31, warp = tid >> 5;
    const int wm = warp >> 2;        // 0..1, m offset wm*64
    const int wn = warp & 3;         // 0..3, n offset wn*32

#pragma unroll
    for (int a = 0; a < 4; a++)
#pragma unroll
        for (int b = 0; b < 4; b++)
#pragma unroll
            for (int c = 0; c < 4; c++) acc[a][b][c] = 0.f;

    const int a_row = wm * 64 + (lane & 15);
    const int a_hi  = lane >> 4;
    const int b_row = wn * 32 + (lane & 7) + ((lane >> 4) & 1) * 8;
    const int b_hi  = (lane >> 3) & 1;

    load_stage(smem_base,       Ab, As, Bb, Bs, m0, n0, 0,   tid);
    load_stage(smem_base + STG, Ab, As, Bb, Bs, m0, n0, GBK, tid);

    int s = 0;
    for (int t = 0; t < NKT; t++) {
        if (t + 1 < NKT) asm volatile("cp.async.wait_group 1;" ::: "memory");
        else             asm volatile("cp.async.wait_group 0;" ::: "memory");
        __syncthreads();   // tile t resident; buffer of t-1 drained by all warps

        if (t + 2 < NKT) {
            int s2 = s + 2; if (s2 >= NSTG) s2 -= NSTG;
            load_stage(smem_base + s2 * STG, Ab, As, Bb, Bs, m0, n0, (t + 2) * GBK, tid);
        }

        uint32_t sb = smem_base + s * STG;
#pragma unroll
        for (int kk = 0; kk < 2; kk++) {
            unsigned Bfb[4][2], Bfs[4][2];
#pragma unroll
            for (int bt = 0; bt < 2; bt++) {
                int r = b_row + bt * 16;
                uint32_t off = sw_off(r, kk * 2 + b_hi);
                ldsm4(Bfb[bt*2][0], Bfb[bt*2][1], Bfb[bt*2+1][0], Bfb[bt*2+1][1],
                      sb + OFF_BB + off);
                ldsm4(Bfs[bt*2][0], Bfs[bt*2][1], Bfs[bt*2+1][0], Bfs[bt*2+1][1],
                      sb + OFF_BS + off);
            }
            {
                unsigned Afb[4][4];
#pragma unroll
                for (int mt = 0; mt < 4; mt++) {
                    int r = a_row + mt * 16;
                    uint32_t off = sw_off(r, kk * 2 + a_hi);
                    ldsm4(Afb[mt][0], Afb[mt][1], Afb[mt][2], Afb[mt][3], sb + OFF_AB + off);
                }
#pragma unroll
                for (int mt = 0; mt < 4; mt++)
#pragma unroll
                    for (int nt = 0; nt < 4; nt++) {
                        mma16(acc[mt][nt], Afb[mt], Bfb[nt]);  // big*big
                        mma16(acc[mt][nt], Afb[mt], Bfs[nt]);  // big*small
                    }
            }
            {
                unsigned Afs[4][4];
#pragma unroll
                for (int mt = 0; mt < 4; mt++) {
                    int r = a_row + mt * 16;
                    uint32_t off = sw_off(r, kk * 2 + a_hi);
                    ldsm4(Afs[mt][0], Afs[mt][1], Afs[mt][2], Afs[mt][3], sb + OFF_AS + off);
                }
#pragma unroll
                for (int mt = 0; mt < 4; mt++)
#pragma unroll
                    for (int nt = 0; nt < 4; nt++)
                        mma16(acc[mt][nt], Afs[mt], Bfb[nt]);  // small*big
            }
        }
        s = (s + 1 == NSTG) ? 0 : s + 1;
    }
}

// ---- QKV GEMM: N=2304 as 18 blocks of 128; scatter epilogue ----
__global__ __launch_bounds__(256, 2)
void qkv_gemm_kernel(const float* __restrict__ q_bias, const float* __restrict__ v_bias) {
    extern __shared__ char smg[];
    const int bx = blockIdx.x, m0 = blockIdx.y * 128;
    float acc[4][4][4];
    gemm_mainloop(g_xb, g_xs, g_wqb, g_wqs, m0, bx * 128, smem_u32(smg), acc);

    const int lane = threadIdx.x & 31, warp = threadIdx.x >> 5;
    const int tig = lane & 3, gid = lane >> 2;
    const int wm = warp >> 2, wn = warp & 3;
    const float scale = 0.125f;

#pragma unroll
    for (int mt = 0; mt < 4; mt++)
#pragma unroll
        for (int nt = 0; nt < 4; nt++) {
            int n_g = bx * 128 + wn * 32 + nt * 8 + tig * 2;
            int which = n_g / CDIM;
            int wi = n_g % CDIM;
            int h = wi >> 6, d = wi & 63;
#pragma unroll
            for (int half = 0; half < 2; half++) {
                int m = m0 + wm * 64 + mt * 16 + gid + half * 8;
                int b_i = m / NTOK, tok = m % NTOK;
                size_t base = ((size_t)(b_i * HEADS + h) * NTOK + tok) * HD + d;
                float2 o = make_float2(acc[mt][nt][half * 2 + 0], acc[mt][nt][half * 2 + 1]);
                if (which == 0) {
                    float2 qb = *(const float2*)&q_bias[h * HD + d];
                    o.x = (o.x + qb.x) * scale;
                    o.y = (o.y + qb.y) * scale;
                    *(float2*)&g_q[base] = o;
                } else if (which == 1) {
                    *(float2*)&g_k[base] = o;
                } else {
                    float2 vb = *(const float2*)&v_bias[h * HD + d];
                    o.x += vb.x; o.y += vb.y;
                    *(float2*)&g_v[base] = o;
                }
            }
        }
}

// ---- output projection GEMM ----
__global__ __launch_bounds__(256, 2)
void proj_gemm_kernel(const float* __restrict__ bias, float* __restrict__ out) {
    extern __shared__ char smg[];
    const int bx = blockIdx.x, m0 = blockIdx.y * 128;
    float acc[4][4][4];
    gemm_mainloop(g_aob, g_aos, g_wpb, g_wps, m0, bx * 128, smem_u32(smg), acc);

    const int lane = threadIdx.x & 31, warp = threadIdx.x >> 5;
    const int tig = lane & 3, gid = lane >> 2;
    const int wm = warp >> 2, wn = warp & 3;

#pragma unroll
    for (int mt = 0; mt < 4; mt++)
#pragma unroll
        for (int nt = 0; nt < 4; nt++) {
            int ng = bx * 128 + wn * 32 + nt * 8 + tig * 2;
            float2 bb = *(const float2*)&bias[ng];
#pragma unroll
            for (int half = 0; half < 2; half++) {
                int m = m0 + wm * 64 + mt * 16 + gid + half * 8;
                float2 o = make_float2(acc[mt][nt][half * 2 + 0] + bb.x,
                                       acc[mt][nt][half * 2 + 1] + bb.y);
                *(float2*)&out[(size_t)m * CDIM + ng] = o;
            }
        }
}

// ======================= attention (q-blocked, d-outer QK loop) =======================
#define QBLK 4
#define NQG  ((NTOK + QBLK - 1) / QBLK)  // 50
#define KPAD 68
#define PSTR 5
#define SM_K (NTOK * KPAD)
#define SM_V (NTOK * HD)
#define SM_P (8 * 200 * PSTR)
#define SM_Q (8 * QBLK * HD)
#define SMEM_ATTN ((SM_K + SM_V + SM_P + SM_Q) * 4)  // 144208 B

__global__ __launch_bounds__(256)
void attn_kernel() {
    extern __shared__ float sma[];
    float* Ks = sma;
    float* Vs = Ks + SM_K;
    float* Ps = Vs + SM_V;
    float* Qs = Ps + SM_P;

    const int bh = blockIdx.x;
    const int b = bh / HEADS, h = bh % HEADS;
    const int tid = threadIdx.x;
    const float* kb = g_k + (size_t)bh * NTOK * HD;
    const float* vb = g_v + (size_t)bh * NTOK * HD;
    const float* qg = g_q + (size_t)bh * NTOK * HD;
    const float* rb = g_rb + (size_t)h * NTOK * NTOK;

    for (int e = tid; e < NTOK * (HD / 4); e += 256) {
        int row = e >> 4, c4 = (e & 15) << 2;
        *(float4*)&Ks[row * KPAD + c4] = *(const float4*)&kb[row * HD + c4];
        *(float4*)&Vs[row * HD + c4]   = *(const float4*)&vb[row * HD + c4];
    }
    __syncthreads();

    const int w = tid >> 5, lane = tid & 31;
    float* Pw = Ps + w * 200 * PSTR;
    float* Qw = Qs + w * QBLK * HD;

    for (int qgi = w; qgi < NQG; qgi += 8) {
        const int q0 = qgi * QBLK;
#pragma unroll
        for (int qq = 0; qq < QBLK; qq++) {
            int q = q0 + qq;
            float2 qv = (q < NTOK) ? *(const float2*)&qg[(size_t)q * HD + lane * 2]
                                   : make_float2(0.f, 0.f);
            *(float2*)&Qw[qq * HD + lane * 2] = qv;
        }
        __syncwarp();

        float s[QBLK][7];
#pragma unroll
        for (int qq = 0; qq < QBLK; qq++)
#pragma unroll
            for (int i = 0; i < 7; i++) s[qq][i] = 0.f;

        // d-outer: q fragments live in registers across the 7 key rows
#pragma unroll 4
        for (int d4 = 0; d4 < 16; d4++) {
            float4 qf0 = *(const float4*)&Qw[0 * HD + d4 * 4];
            float4 qf1 = *(const float4*)&Qw[1 * HD + d4 * 4];
            float4 qf2 = *(const float4*)&Qw[2 * HD + d4 * 4];
            float4 qf3 = *(const float4*)&Qw[3 * HD + d4 * 4];
#pragma unroll
            for (int i = 0; i < 7; i++) {
                int m = lane + i * 32;
                if (m < NTOK) {
                    float4 kk = *(const float4*)&Ks[m * KPAD + d4 * 4];
                    s[0][i] = fmaf(kk.x, qf0.x, fmaf(kk.y, qf0.y, fmaf(kk.z, qf0.z, fmaf(kk.w, qf0.w, s[0][i]))));
                    s[1][i] = fmaf(kk.x, qf1.x, fmaf(kk.y, qf1.y, fmaf(kk.z, qf1.z, fmaf(kk.w, qf1.w, s[1][i]))));
                    s[2][i] = fmaf(kk.x, qf2.x, fmaf(kk.y, qf2.y, fmaf(kk.z, qf2.z, fmaf(kk.w, qf2.w, s[2][i]))));
                    s[3][i] = fmaf(kk.x, qf3.x, fmaf(kk.y, qf3.y, fmaf(kk.z, qf3.z, fmaf(kk.w, qf3.w, s[3][i]))));
                }
            }
        }
        // add rel bias / mask invalid
#pragma unroll
        for (int qq = 0; qq < QBLK; qq++) {
            int q = q0 + qq;
#pragma unroll
            for (int i = 0; i < 7; i++) {
                int m = lane + i * 32;
                if (m < NTOK) s[qq][i] += (q < NTOK) ? rb[(size_t)q * NTOK + m] : 0.f;
                else          s[qq][i] = -1e30f;
            }
        }
#pragma unroll
        for (int qq = 0; qq < QBLK; qq++) {
            float mx = s[qq][0];
#pragma unroll
            for (int i = 1; i < 7; i++) mx = fmaxf(mx, s[qq][i]);
#pragma unroll
            for (int o = 16; o > 0; o >>= 1) mx = fmaxf(mx, __shfl_xor_sync(0xffffffffu, mx, o));
            float sum = 0.f;
#pragma unroll
            for (int i = 0; i < 7; i++) {
                int m = lane + i * 32;
                s[qq][i] = (m < NTOK) ? __expf(s[qq][i] - mx) : 0.f;
                sum += s[qq][i];
            }
#pragma unroll
            for (int o = 16; o > 0; o >>= 1) sum += __shfl_xor_sync(0xffffffffu, sum, o);
            float inv = 1.f / sum;
#pragma unroll
            for (int i = 0; i < 7; i++) {
                int m = lane + i * 32;
                if (m < NTOK) Pw[m * PSTR + qq] = s[qq][i] * inv;
            }
        }
        __syncwarp();

        float2 o2[QBLK] = {{0.f,0.f},{0.f,0.f},{0.f,0.f},{0.f,0.f}};
        for (int m = 0; m < NTOK; m++) {
            float2 vv = *(const float2*)&Vs[m * HD + lane * 2];
            float p0 = Pw[m * PSTR + 0];
            float p1 = Pw[m * PSTR + 1];
            float p2 = Pw[m * PSTR + 2];
            float p3 = Pw[m * PSTR + 3];
            o2[0].x = fmaf(p0, vv.x, o2[0].x); o2[0].y = fmaf(p0, vv.y, o2[0].y);
            o2[1].x = fmaf(p1, vv.x, o2[1].x); o2[1].y = fmaf(p1, vv.y, o2[1].y);
            o2[2].x = fmaf(p2, vv.x, o2[2].x); o2[2].y = fmaf(p2, vv.y, o2[2].y);
            o2[3].x = fmaf(p3, vv.x, o2[3].x); o2[3].y = fmaf(p3, vv.y, o2[3].y);
        }
#pragma unroll
        for (int qq = 0; qq < QBLK; qq++) {
            int q = q0 + qq;
            if (q < NTOK) {
                size_t base = ((size_t)(b * NTOK + q)) * CDIM + h * HD + lane * 2;
                __nv_bfloat16 b0,s0,b1,s1;
                split1(o2[qq].x, b0, s0);
                split1(o2[qq].y, b1, s1);
                *(__nv_bfloat162*)&g_aob[base] = {b0, b1};
                *(__nv_bfloat162*)&g_aos[base] = {s0, s1};
            }
        }
        __syncwarp();
    }
}

// ======================= launch =======================
extern "C" void kernel_launch(void* const* d_in, const int* in_sizes, int n_in,
                              void* d_out, int out_size) {
    const float* x        = (const float*)d_in[0];
    const float* qkv_w    = (const float*)d_in[1];
    const float* q_bias   = (const float*)d_in[2];
    const float* v_bias   = (const float*)d_in[3];
    const float* rel_tab  = (const float*)d_in[4];
    const float* proj_w   = (const float*)d_in[5];
    const float* proj_b   = (const float*)d_in[6];
    const int*   rel_idx  = (const int*)d_in[7];
    float* out = (float*)d_out;

    static_assert(MROWS % 128 == 0 && N_QKV % 128 == 0 && CDIM % 128 == 0, "tiling");

    cudaFuncSetAttribute(qkv_gemm_kernel,  cudaFuncAttributeMaxDynamicSharedMemorySize, SMEM_GEMM);
    cudaFuncSetAttribute(proj_gemm_kernel, cudaFuncAttributeMaxDynamicSharedMemorySize, SMEM_GEMM);
    cudaFuncSetAttribute(attn_kernel,      cudaFuncAttributeMaxDynamicSharedMemorySize, SMEM_ATTN);

    relbias_kernel<<<(NTOK * NTOK + 255) / 256, 256>>>(rel_tab, rel_idx);

    {
        __nv_bfloat16 *xb, *xs, *wqb, *wqs, *wpb, *wps;
        cudaGetSymbolAddress((void**)&xb,  g_xb);
        cudaGetSymbolAddress((void**)&xs,  g_xs);
        cudaGetSymbolAddress((void**)&wqb, g_wqb);
        cudaGetSymbolAddress((void**)&wqs, g_wqs);
        cudaGetSymbolAddress((void**)&wpb, g_wpb);
        cudaGetSymbolAddress((void**)&wps, g_wps);
        int n4x = MROWS * KDIM / 4;
        split_kernel<<<(n4x + 255) / 256, 256>>>(x, xb, xs, n4x);
        int n4q = N_QKV * KDIM / 4;
        split_kernel<<<(n4q + 255) / 256, 256>>>(qkv_w, wqb, wqs, n4q);
        int n4p = CDIM * CDIM / 4;
        split_kernel<<<(n4p + 255) / 256, 256>>>(proj_w, wpb, wps, n4p);
    }

    {
        dim3 grid(N_QKV / 128, MROWS / 128);  // (18, 197)
        qkv_gemm_kernel<<<grid, 256, SMEM_GEMM>>>(q_bias, v_bias);
    }

    attn_kernel<<<BATCH * HEADS, 256, SMEM_ATTN>>>();

    {
        dim3 grid(CDIM / 128, MROWS / 128);   // (6, 197)
        proj_gemm_kernel<<<grid, 256, SMEM_GEMM>>>(proj_b, out);
    }
}